// round 3
// baseline (speedup 1.0000x reference)
#include <cuda_runtime.h>
#include <math.h>

#define H 128
#define NCHK 8000
#define NVAR 16000
#define EDGES 60000
#define NITER 10
#define LN_EPS 1e-6f

typedef unsigned long long u64;

// ---------------- scratch (device globals) ----------------
__device__ float g_hc[NCHK * H];
__device__ float g_hv[NVAR * H];
__device__ float g_Pc[NCHK * 256];
__device__ float g_Pv[NVAR * 256];
__device__ float g_aggc[NCHK * H];
__device__ float g_aggv[NVAR * H];
__device__ float g_updc[NCHK * H];
__device__ float g_updv[NVAR * H];
__device__ float g_xac[NCHK * 384];
__device__ float g_hac[NCHK * 384];
__device__ float g_xav[NVAR * 384];
__device__ float g_hav[NVAR * 384];
__device__ int g_cnt_c[NCHK], g_cnt_v[NVAR];
__device__ int g_rp_c[NCHK + 1], g_rp_v[NVAR + 1];
__device__ int g_cur_c[NCHK], g_cur_v[NVAR];
__device__ int g_el_c[EDGES], g_el_v[EDGES];

__device__ __forceinline__ float elu_f(float x) { return x > 0.f ? x : expm1f(x); }
__device__ __forceinline__ float sig_f(float x) { return 1.f / (1.f + expf(-x)); }

__device__ __forceinline__ u64 pack2(float lo, float hi) {
    u64 p;
    asm("mov.b64 %0, {%1, %2};" : "=l"(p) : "f"(lo), "f"(hi));
    return p;
}
__device__ __forceinline__ void fma2(u64& d, u64 a, u64 b) {
    asm("fma.rn.f32x2 %0, %1, %2, %0;" : "+l"(d) : "l"(a), "l"(b));
}
__device__ __forceinline__ float2 unpack2(u64 p) {
    float2 r;
    asm("mov.b64 {%0, %1}, %2;" : "=f"(r.x), "=f"(r.y) : "l"(p));
    return r;
}

// ---------------- init: h = LN(0.1*feat * Win + bin); also zeroes CSR cnt ----------------
__global__ void init_kernel(const float* __restrict__ feat, const float* __restrict__ Win,
                            const float* __restrict__ bin, const float* __restrict__ g,
                            const float* __restrict__ bln, float* __restrict__ h,
                            int* __restrict__ cnt, int ncnt)
{
    __shared__ float red[4];
    __shared__ float red2[4];
    const int n = blockIdx.x;
    const int j = threadIdx.x;
    if (j == 0 && n < ncnt) cnt[n] = 0;

    const float x = 0.1f * feat[n];
    const float val = x * Win[j] + bin[j];

    float s = val;
    #pragma unroll
    for (int o = 16; o > 0; o >>= 1) s += __shfl_xor_sync(0xffffffff, s, o);
    if ((j & 31) == 0) red[j >> 5] = s;
    __syncthreads();
    const float m = (red[0] + red[1] + red[2] + red[3]) * (1.0f / 128.0f);

    const float d = val - m;
    float s2 = d * d;
    #pragma unroll
    for (int o = 16; o > 0; o >>= 1) s2 += __shfl_xor_sync(0xffffffff, s2, o);
    if ((j & 31) == 0) red2[j >> 5] = s2;
    __syncthreads();
    const float v = (red2[0] + red2[1] + red2[2] + red2[3]) * (1.0f / 128.0f);

    h[(size_t)n * H + j] = g[j] * d * rsqrtf(v + LN_EPS) + bln[j];
}

// ---------------- CSR build ----------------
__global__ void hist_kernel(const int* __restrict__ tgt, int* __restrict__ cnt, int nE)
{
    int e = blockIdx.x * blockDim.x + threadIdx.x;
    if (e < nE) atomicAdd(&cnt[tgt[e]], 1);
}

__device__ void scan_impl(const int* __restrict__ cnt, int* __restrict__ rowptr,
                          int* __restrict__ cursor, int n)
{
    __shared__ int wsum[32];
    __shared__ int tot_s;
    const int tid = threadIdx.x;
    const int lane = tid & 31, w = tid >> 5;
    int carry = 0;
    for (int base = 0; base < n; base += 1024) {
        const int i = base + tid;
        int x = (i < n) ? cnt[i] : 0;
        int v = x;
        #pragma unroll
        for (int off = 1; off < 32; off <<= 1) {
            int t = __shfl_up_sync(0xffffffff, v, off);
            if (lane >= off) v += t;
        }
        if (lane == 31) wsum[w] = v;
        __syncthreads();
        if (w == 0) {
            int t = wsum[lane];
            #pragma unroll
            for (int off = 1; off < 32; off <<= 1) {
                int u = __shfl_up_sync(0xffffffff, t, off);
                if (lane >= off) t += u;
            }
            wsum[lane] = t;
            if (lane == 31) tot_s = t;
        }
        __syncthreads();
        const int incl = v + (w > 0 ? wsum[w - 1] : 0);
        if (i < n) { int ex = carry + incl - x; rowptr[i] = ex; cursor[i] = ex; }
        carry += tot_s;
        __syncthreads();
    }
    if (tid == 0) rowptr[n] = carry;
}

__global__ void scan2_kernel(const int* cA, int* rA, int* uA, int nA,
                             const int* cB, int* rB, int* uB, int nB)
{
    if (blockIdx.x == 0) scan_impl(cA, rA, uA, nA);
    else                 scan_impl(cB, rB, uB, nB);
}

__global__ void fill_kernel(const int* __restrict__ src, const int* __restrict__ tgt,
                            int* __restrict__ cursor, int* __restrict__ list, int nE)
{
    int e = blockIdx.x * blockDim.x + threadIdx.x;
    if (e < nE) {
        int p = atomicAdd(&cursor[tgt[e]], 1);
        list[p] = src[e];
    }
}

// ================= GEMM v3: duplicated-W SMEM, packed f32x2, chunk-outer =================
// out[r, c*128+col] = act( sum_k A[r,k] * Wc[k,col] + bc[col] ),  K=128 per chunk.
// 256 threads; thread (rg=tid>>4, cg=tid&15) computes RPT rows x 8 cols.
// Wd (SMEM) holds chunk weights pre-duplicated as float2(w,w) -> inner loop has zero packing.
// Blocks are assigned chunks round-robin (blockIdx % NCH) so all SMs stay busy.
template<int NCH, int RT, bool ACT>
__global__ void __launch_bounds__(256, 1)
pgemmN_kernel(const float* __restrict__ A,
              const float* __restrict__ W0, int ld0, const float* __restrict__ b0,
              const float* __restrict__ W1, int ld1, const float* __restrict__ b1,
              const float* __restrict__ W2, int ld2, const float* __restrict__ b2,
              float* __restrict__ out, int outW, int nRows)
{
    constexpr int RPT = RT / 16;
    constexpr int NP  = RPT / 2;
    constexpr int XST = RT + 4;      // floats; (XST*4)%16==0 for LDS.128 on xp

    extern __shared__ float sm[];
    float2* Wd = (float2*)sm;              // 128*128 float2 = 131072 B
    float*  XsT = sm + 2 * 128 * 128;      // 128 * XST floats

    const int tid = threadIdx.x;
    const int cg = tid & 15;
    const int rg = tid >> 4;

    const float* Wp[3] = {W0, W1, W2};
    const int    ldw[3] = {ld0, ld1, ld2};
    const float* bp[3] = {b0, b1, b2};

    const int c    = blockIdx.x % NCH;
    const int bpc  = gridDim.x / NCH;
    const int t0   = blockIdx.x / NCH;
    const int nTiles = (nRows + RT - 1) / RT;

    // load duplicated weights for this block's chunk (once per launch)
    {
        const float* w = Wp[c];
        const int l = ldw[c];
        for (int idx = tid; idx < 128 * 128; idx += 256) {
            const float v = w[(size_t)(idx >> 7) * l + (idx & 127)];
            Wd[idx] = make_float2(v, v);
        }
    }
    float bcol[8];
    #pragma unroll
    for (int j = 0; j < 8; j++) bcol[j] = bp[c] ? bp[c][8 * cg + j] : 0.f;
    __syncthreads();

    for (int tile = t0; tile < nTiles; tile += bpc) {
        const int row0 = tile * RT;
        for (int idx = tid; idx < RT * 128; idx += 256) {
            const int e = idx >> 7;
            const int k = idx & 127;
            int r = row0 + e;
            if (r >= nRows) r = nRows - 1;
            XsT[k * XST + e] = A[(size_t)r * 128 + k];
        }
        __syncthreads();

        u64 acc[NP][8];
        #pragma unroll
        for (int p = 0; p < NP; p++)
            #pragma unroll
            for (int j = 0; j < 8; j++) acc[p][j] = pack2(bcol[j], bcol[j]);

        #pragma unroll 4
        for (int k = 0; k < 128; k++) {
            const ulonglong2* xr = (const ulonglong2*)&XsT[k * XST + RPT * rg];
            const ulonglong2* wr = (const ulonglong2*)(Wd + k * 128 + 8 * cg);
            u64 xp[NP];
            #pragma unroll
            for (int q = 0; q < NP / 2; q++) {
                const ulonglong2 t = xr[q];
                xp[2 * q] = t.x; xp[2 * q + 1] = t.y;
            }
            u64 wd[8];
            #pragma unroll
            for (int q = 0; q < 4; q++) {
                const ulonglong2 t = wr[q];
                wd[2 * q] = t.x; wd[2 * q + 1] = t.y;
            }
            #pragma unroll
            for (int p = 0; p < NP; p++)
                #pragma unroll
                for (int j = 0; j < 8; j++) fma2(acc[p][j], xp[p], wd[j]);
        }
        __syncthreads();

        #pragma unroll
        for (int p = 0; p < NP; p++) {
            float2 v[8];
            #pragma unroll
            for (int j = 0; j < 8; j++) v[j] = unpack2(acc[p][j]);
            const int r0 = row0 + RPT * rg + 2 * p;
            float* o0 = out + (size_t)r0 * outW + c * 128 + 8 * cg;
            if (r0 < nRows) {
                float4 a, b;
                a.x = ACT ? elu_f(v[0].x) : v[0].x; a.y = ACT ? elu_f(v[1].x) : v[1].x;
                a.z = ACT ? elu_f(v[2].x) : v[2].x; a.w = ACT ? elu_f(v[3].x) : v[3].x;
                b.x = ACT ? elu_f(v[4].x) : v[4].x; b.y = ACT ? elu_f(v[5].x) : v[5].x;
                b.z = ACT ? elu_f(v[6].x) : v[6].x; b.w = ACT ? elu_f(v[7].x) : v[7].x;
                *(float4*)o0 = a; *(float4*)(o0 + 4) = b;
            }
            if (r0 + 1 < nRows) {
                float4 a, b;
                a.x = ACT ? elu_f(v[0].y) : v[0].y; a.y = ACT ? elu_f(v[1].y) : v[1].y;
                a.z = ACT ? elu_f(v[2].y) : v[2].y; a.w = ACT ? elu_f(v[3].y) : v[3].y;
                b.x = ACT ? elu_f(v[4].y) : v[4].y; b.y = ACT ? elu_f(v[5].y) : v[5].y;
                b.z = ACT ? elu_f(v[6].y) : v[6].y; b.w = ACT ? elu_f(v[7].y) : v[7].y;
                float* o1 = o0 + outW;
                *(float4*)o1 = a; *(float4*)(o1 + 4) = b;
            }
        }
    }
}

// K=256 concat GEMM (node update): two k-stages, Wdup reloaded per tile per stage.
template<int RT, bool ACT>
__global__ void __launch_bounds__(256, 1)
pgemmK_kernel(const float* __restrict__ A0, const float* __restrict__ A1,
              const float* __restrict__ W, const float* __restrict__ bias,
              float* __restrict__ out, int nRows)
{
    constexpr int RPT = RT / 16;
    constexpr int NP  = RPT / 2;
    constexpr int XST = RT + 4;

    extern __shared__ float sm[];
    float2* Wd = (float2*)sm;
    float*  XsT = sm + 2 * 128 * 128;

    const int tid = threadIdx.x;
    const int cg = tid & 15;
    const int rg = tid >> 4;
    const int nTiles = (nRows + RT - 1) / RT;

    float bcol[8];
    #pragma unroll
    for (int j = 0; j < 8; j++) bcol[j] = bias[8 * cg + j];

    for (int tile = blockIdx.x; tile < nTiles; tile += gridDim.x) {
        const int row0 = tile * RT;
        u64 acc[NP][8];
        #pragma unroll
        for (int p = 0; p < NP; p++)
            #pragma unroll
            for (int j = 0; j < 8; j++) acc[p][j] = pack2(bcol[j], bcol[j]);

        #pragma unroll
        for (int s = 0; s < 2; s++) {
            __syncthreads();   // previous stage k-loop / previous tile done
            const float* w = W + (size_t)s * 128 * 128;
            for (int idx = tid; idx < 128 * 128; idx += 256) {
                const float v = w[idx];
                Wd[idx] = make_float2(v, v);
            }
            const float* As = s ? A1 : A0;
            for (int idx = tid; idx < RT * 128; idx += 256) {
                const int e = idx >> 7;
                const int k = idx & 127;
                int r = row0 + e;
                if (r >= nRows) r = nRows - 1;
                XsT[k * XST + e] = As[(size_t)r * 128 + k];
            }
            __syncthreads();

            #pragma unroll 4
            for (int k = 0; k < 128; k++) {
                const ulonglong2* xr = (const ulonglong2*)&XsT[k * XST + RPT * rg];
                const ulonglong2* wr = (const ulonglong2*)(Wd + k * 128 + 8 * cg);
                u64 xp[NP];
                #pragma unroll
                for (int q = 0; q < NP / 2; q++) {
                    const ulonglong2 t = xr[q];
                    xp[2 * q] = t.x; xp[2 * q + 1] = t.y;
                }
                u64 wd[8];
                #pragma unroll
                for (int q = 0; q < 4; q++) {
                    const ulonglong2 t = wr[q];
                    wd[2 * q] = t.x; wd[2 * q + 1] = t.y;
                }
                #pragma unroll
                for (int p = 0; p < NP; p++)
                    #pragma unroll
                    for (int j = 0; j < 8; j++) fma2(acc[p][j], xp[p], wd[j]);
            }
        }

        #pragma unroll
        for (int p = 0; p < NP; p++) {
            float2 v[8];
            #pragma unroll
            for (int j = 0; j < 8; j++) v[j] = unpack2(acc[p][j]);
            const int r0 = row0 + RPT * rg + 2 * p;
            float* o0 = out + (size_t)r0 * 128 + 8 * cg;
            if (r0 < nRows) {
                float4 a, b;
                a.x = ACT ? elu_f(v[0].x) : v[0].x; a.y = ACT ? elu_f(v[1].x) : v[1].x;
                a.z = ACT ? elu_f(v[2].x) : v[2].x; a.w = ACT ? elu_f(v[3].x) : v[3].x;
                b.x = ACT ? elu_f(v[4].x) : v[4].x; b.y = ACT ? elu_f(v[5].x) : v[5].x;
                b.z = ACT ? elu_f(v[6].x) : v[6].x; b.w = ACT ? elu_f(v[7].x) : v[7].x;
                *(float4*)o0 = a; *(float4*)(o0 + 4) = b;
            }
            if (r0 + 1 < nRows) {
                float4 a, b;
                a.x = ACT ? elu_f(v[0].y) : v[0].y; a.y = ACT ? elu_f(v[1].y) : v[1].y;
                a.z = ACT ? elu_f(v[2].y) : v[2].y; a.w = ACT ? elu_f(v[3].y) : v[3].y;
                b.x = ACT ? elu_f(v[4].y) : v[4].y; b.y = ACT ? elu_f(v[5].y) : v[5].y;
                b.z = ACT ? elu_f(v[6].y) : v[6].y; b.w = ACT ? elu_f(v[7].y) : v[7].y;
                float* o1 = o0 + 128;
                *(float4*)o1 = a; *(float4*)(o1 + 4) = b;
            }
        }
    }
}

// ---------------- aggregate: out[t] = sum_{e in CSR(t)} elu(Psend[src_e] + Ptgt[t] + b) ----------------
__global__ void agg_kernel(const int* __restrict__ rowptr, const int* __restrict__ srcs,
                           const float* __restrict__ Psend, const float* __restrict__ Ptgt,
                           const float* __restrict__ bias, float* __restrict__ out)
{
    const int t = blockIdx.x;
    const int j = threadIdx.x;
    const float base = Ptgt[(size_t)t * 256 + 128 + j] + bias[j];
    const int beg = rowptr[t], end = rowptr[t + 1];
    float s0 = 0.f, s1 = 0.f;
    int i = beg;
    for (; i + 1 < end; i += 2) {
        const int a = srcs[i];
        const int b = srcs[i + 1];
        s0 += elu_f(base + Psend[(size_t)a * 256 + j]);
        s1 += elu_f(base + Psend[(size_t)b * 256 + j]);
    }
    if (i < end) s0 += elu_f(base + Psend[(size_t)srcs[i] * 256 + j]);
    out[(size_t)t * 128 + j] = s0 + s1;
}

// ---------------- GRU combine ----------------
__global__ void gru_combine_kernel(const float* __restrict__ xa, const float* __restrict__ ha,
                                   float* __restrict__ h, int nNodes)
{
    const int idx = blockIdx.x * blockDim.x + threadIdx.x;
    if (idx >= nNodes * 32) return;
    const int n = idx >> 5;
    const int q = (idx & 31) * 4;
    const float4 xz = *(const float4*)&xa[(size_t)n * 384 + q];
    const float4 xr = *(const float4*)&xa[(size_t)n * 384 + 128 + q];
    const float4 xh = *(const float4*)&xa[(size_t)n * 384 + 256 + q];
    const float4 hz = *(const float4*)&ha[(size_t)n * 384 + q];
    const float4 hr = *(const float4*)&ha[(size_t)n * 384 + 128 + q];
    const float4 hh = *(const float4*)&ha[(size_t)n * 384 + 256 + q];
    float4 ho = *(const float4*)&h[(size_t)n * 128 + q];

    float z, r, c;
    z = sig_f(xz.x + hz.x); r = sig_f(xr.x + hr.x); c = tanhf(xh.x + r * hh.x); ho.x = z * ho.x + (1.f - z) * c;
    z = sig_f(xz.y + hz.y); r = sig_f(xr.y + hr.y); c = tanhf(xh.y + r * hh.y); ho.y = z * ho.y + (1.f - z) * c;
    z = sig_f(xz.z + hz.z); r = sig_f(xr.z + hr.z); c = tanhf(xh.z + r * hh.z); ho.z = z * ho.z + (1.f - z) * c;
    z = sig_f(xz.w + hz.w); r = sig_f(xr.w + hr.w); c = tanhf(xh.w + r * hh.w); ho.w = z * ho.w + (1.f - z) * c;
    *(float4*)&h[(size_t)n * 128 + q] = ho;
}

// ---------------- final ----------------
__global__ void final_kernel(const float* __restrict__ hv, const float* __restrict__ Wf,
                             const float* __restrict__ bf, float* __restrict__ out, int n)
{
    const int gw = (blockIdx.x * blockDim.x + threadIdx.x) >> 5;
    const int lane = threadIdx.x & 31;
    if (gw >= n) return;
    const float* row = hv + (size_t)gw * H;
    float s = row[lane] * Wf[lane] + row[lane + 32] * Wf[lane + 32]
            + row[lane + 64] * Wf[lane + 64] + row[lane + 96] * Wf[lane + 96];
    #pragma unroll
    for (int o = 16; o > 0; o >>= 1) s += __shfl_xor_sync(0xffffffff, s, o);
    if (lane == 0) out[gw] = s + bf[0];
}

// ---------------- host ----------------
#define SMEM_N ((2 * 128 * 128 + 128 * 132) * 4)   // 198,656 (RT=128)
#define SMEM_K ((2 * 128 * 128 + 128 * 68) * 4)    // 165,888 (RT=64)

static inline int mini(int a, int b) { return a < b ? a : b; }

extern "C" void kernel_launch(void* const* d_in, const int* in_sizes, int n_in,
                              void* d_out, int out_size)
{
    const float* check_feats = (const float*)d_in[0];
    const float* var_feats   = (const float*)d_in[1];
    const int*   c2v_src     = (const int*)d_in[2];
    const int*   c2v_tgt     = (const int*)d_in[3];
    const int*   v2c_src     = (const int*)d_in[4];
    const int*   v2c_tgt     = (const int*)d_in[5];
    const float* Wc_in  = (const float*)d_in[6];
    const float* bc_in  = (const float*)d_in[7];
    const float* Wv_in  = (const float*)d_in[8];
    const float* bv_in  = (const float*)d_in[9];
    const float* gc_ln  = (const float*)d_in[10];
    const float* bc_ln  = (const float*)d_in[11];
    const float* gv_ln  = (const float*)d_in[12];
    const float* bv_ln  = (const float*)d_in[13];
    const float* Wmsg_c = (const float*)d_in[14];
    const float* bmsg_c = (const float*)d_in[15];
    const float* Wmsg_v = (const float*)d_in[16];
    const float* bmsg_v = (const float*)d_in[17];
    const float* Wns_c  = (const float*)d_in[18];
    const float* bns_c  = (const float*)d_in[19];
    const float* Wns_v  = (const float*)d_in[20];
    const float* bns_v  = (const float*)d_in[21];
    const float* Wg_c   = (const float*)d_in[22];
    const float* Ug_c   = (const float*)d_in[23];
    const float* bg_c   = (const float*)d_in[24];
    const float* Wg_v   = (const float*)d_in[25];
    const float* Ug_v   = (const float*)d_in[26];
    const float* bg_v   = (const float*)d_in[27];
    const float* Wf     = (const float*)d_in[28];
    const float* bf     = (const float*)d_in[29];

    const int NCn = in_sizes[0];
    const int NVn = in_sizes[1];
    const int E   = in_sizes[2];

    float *hc, *hv, *Pc, *Pv, *aggc, *aggv, *updc, *updv, *xac, *hac, *xav, *hav;
    int *cnt_c, *cnt_v, *rp_c, *rp_v, *cur_c, *cur_v, *el_c, *el_v;
    cudaGetSymbolAddress((void**)&hc,   g_hc);
    cudaGetSymbolAddress((void**)&hv,   g_hv);
    cudaGetSymbolAddress((void**)&Pc,   g_Pc);
    cudaGetSymbolAddress((void**)&Pv,   g_Pv);
    cudaGetSymbolAddress((void**)&aggc, g_aggc);
    cudaGetSymbolAddress((void**)&aggv, g_aggv);
    cudaGetSymbolAddress((void**)&updc, g_updc);
    cudaGetSymbolAddress((void**)&updv, g_updv);
    cudaGetSymbolAddress((void**)&xac,  g_xac);
    cudaGetSymbolAddress((void**)&hac,  g_hac);
    cudaGetSymbolAddress((void**)&xav,  g_xav);
    cudaGetSymbolAddress((void**)&hav,  g_hav);
    cudaGetSymbolAddress((void**)&cnt_c, g_cnt_c);
    cudaGetSymbolAddress((void**)&cnt_v, g_cnt_v);
    cudaGetSymbolAddress((void**)&rp_c,  g_rp_c);
    cudaGetSymbolAddress((void**)&rp_v,  g_rp_v);
    cudaGetSymbolAddress((void**)&cur_c, g_cur_c);
    cudaGetSymbolAddress((void**)&cur_v, g_cur_v);
    cudaGetSymbolAddress((void**)&el_c,  g_el_c);
    cudaGetSymbolAddress((void**)&el_v,  g_el_v);

    auto msgGemm  = pgemmN_kernel<2, 128, false>;
    auto gruGemm  = pgemmN_kernel<3, 128, false>;
    auto nodeGemm = pgemmK_kernel<64, true>;
    cudaFuncSetAttribute(msgGemm,  cudaFuncAttributeMaxDynamicSharedMemorySize, SMEM_N);
    cudaFuncSetAttribute(gruGemm,  cudaFuncAttributeMaxDynamicSharedMemorySize, SMEM_N);
    cudaFuncSetAttribute(nodeGemm, cudaFuncAttributeMaxDynamicSharedMemorySize, SMEM_K);

    // grids
    const int tV = (NVn + 127) / 128, tC = (NCn + 127) / 128;
    const int gMsgV = 2 * mini(tV, 74),  gMsgC = 2 * mini(tC, 74);
    const int gGruV = 3 * mini(tV, 49),  gGruC = 3 * mini(tC, 49);
    const int gNodeV = mini((NVn + 63) / 64, 148);
    const int gNodeC = mini((NCn + 63) / 64, 148);
    const int gEh = (E + 255) / 256;

    // ---- init node states (also zero CSR counters) ----
    init_kernel<<<NCn, 128>>>(check_feats, Wc_in, bc_in, gc_ln, bc_ln, hc, cnt_c, NCn);
    init_kernel<<<NVn, 128>>>(var_feats,  Wv_in, bv_in, gv_ln, bv_ln, hv, cnt_v, NVn);

    // ---- CSR histogram + scan (fills come later; not needed until agg) ----
    hist_kernel<<<gEh, 256>>>(v2c_tgt, cnt_c, E);
    hist_kernel<<<gEh, 256>>>(c2v_tgt, cnt_v, E);
    scan2_kernel<<<2, 1024>>>(cnt_c, rp_c, cur_c, NCn, cnt_v, rp_v, cur_v, NVn);

    bool first = true;
    for (int it = 0; it < NITER; it++) {
        // message projections (launch #6 = this kernel, for ncu)
        msgGemm<<<gMsgV, 256, SMEM_N>>>(
            hv, Wmsg_c, 128, nullptr, Wmsg_v + 128 * 128, 128, nullptr,
            nullptr, 0, nullptr, Pv, 256, NVn);
        msgGemm<<<gMsgC, 256, SMEM_N>>>(
            hc, Wmsg_v, 128, nullptr, Wmsg_c + 128 * 128, 128, nullptr,
            nullptr, 0, nullptr, Pc, 256, NCn);

        if (first) {
            fill_kernel<<<gEh, 256>>>(v2c_src, v2c_tgt, cur_c, el_c, E);
            fill_kernel<<<gEh, 256>>>(c2v_src, c2v_tgt, cur_v, el_v, E);
            first = false;
        }

        agg_kernel<<<NCn, 128>>>(rp_c, el_c, Pv, Pc, bmsg_c, aggc);
        agg_kernel<<<NVn, 128>>>(rp_v, el_v, Pc, Pv, bmsg_v, aggv);

        nodeGemm<<<gNodeC, 256, SMEM_K>>>(hc, aggc, Wns_c, bns_c, updc, NCn);
        nodeGemm<<<gNodeV, 256, SMEM_K>>>(hv, aggv, Wns_v, bns_v, updv, NVn);

        gruGemm<<<gGruC, 256, SMEM_N>>>(
            updc, Wg_c, 384, bg_c, Wg_c + 128, 384, bg_c + 128,
            Wg_c + 256, 384, bg_c + 256, xac, 384, NCn);
        gruGemm<<<gGruC, 256, SMEM_N>>>(
            hc, Ug_c, 384, bg_c + 384, Ug_c + 128, 384, bg_c + 384 + 128,
            Ug_c + 256, 384, bg_c + 384 + 256, hac, 384, NCn);
        gru_combine_kernel<<<(NCn * 32 + 255) / 256, 256>>>(xac, hac, hc, NCn);

        gruGemm<<<gGruV, 256, SMEM_N>>>(
            updv, Wg_v, 384, bg_v, Wg_v + 128, 384, bg_v + 128,
            Wg_v + 256, 384, bg_v + 256, xav, 384, NVn);
        gruGemm<<<gGruV, 256, SMEM_N>>>(
            hv, Ug_v, 384, bg_v + 384, Ug_v + 128, 384, bg_v + 384 + 128,
            Ug_v + 256, 384, bg_v + 384 + 256, hav, 384, NVn);
        gru_combine_kernel<<<(NVn * 32 + 255) / 256, 256>>>(xav, hav, hv, NVn);
    }

    final_kernel<<<(NVn * 32 + 127) / 128, 128>>>(hv, Wf, bf, (float*)d_out, NVn);
}

// round 4
// speedup vs baseline: 2.4257x; 2.4257x over previous
#include <cuda_runtime.h>
#include <math.h>

#define H 128
#define NCHK 8000
#define NVAR 16000
#define EDGES 60000
#define NITER 10
#define LN_EPS 1e-6f

typedef unsigned long long u64;

// ---------------- scratch (device globals) ----------------
__device__ float g_hc[NCHK * H];
__device__ float g_hv[NVAR * H];
__device__ float g_Pc[NCHK * 256];
__device__ float g_Pv[NVAR * 256];
__device__ float g_aggc[NCHK * H];
__device__ float g_aggv[NVAR * H];
__device__ float g_updc[NCHK * H];
__device__ float g_updv[NVAR * H];
__device__ float g_xac[NCHK * 384];
__device__ float g_hac[NCHK * 384];
__device__ float g_xav[NVAR * 384];
__device__ float g_hav[NVAR * 384];
__device__ int g_cnt_c[NCHK], g_cnt_v[NVAR];
__device__ int g_rp_c[NCHK + 1], g_rp_v[NVAR + 1];
__device__ int g_cur_c[NCHK], g_cur_v[NVAR];
__device__ int g_el_c[EDGES], g_el_v[EDGES];

__device__ __forceinline__ float elu_f(float x) { return x > 0.f ? x : expm1f(x); }
__device__ __forceinline__ float sig_f(float x) { return 1.f / (1.f + expf(-x)); }

__device__ __forceinline__ u64 pack2(float lo, float hi) {
    u64 p;
    asm("mov.b64 %0, {%1, %2};" : "=l"(p) : "f"(lo), "f"(hi));
    return p;
}
__device__ __forceinline__ void fma2(u64& d, u64 a, u64 b) {
    asm("fma.rn.f32x2 %0, %1, %2, %0;" : "+l"(d) : "l"(a), "l"(b));
}
__device__ __forceinline__ float2 unpack2(u64 p) {
    float2 r;
    asm("mov.b64 {%0, %1}, %2;" : "=f"(r.x), "=f"(r.y) : "l"(p));
    return r;
}

// ---------------- init: h = LN(0.1*feat * Win + bin); also zeroes CSR cnt ----------------
__global__ void init_kernel(const float* __restrict__ feat, const float* __restrict__ Win,
                            const float* __restrict__ bin, const float* __restrict__ g,
                            const float* __restrict__ bln, float* __restrict__ h,
                            int* __restrict__ cnt, int ncnt)
{
    __shared__ float red[4];
    __shared__ float red2[4];
    const int n = blockIdx.x;
    const int j = threadIdx.x;
    if (j == 0 && n < ncnt) cnt[n] = 0;

    const float x = 0.1f * feat[n];
    const float val = x * Win[j] + bin[j];

    float s = val;
    #pragma unroll
    for (int o = 16; o > 0; o >>= 1) s += __shfl_xor_sync(0xffffffff, s, o);
    if ((j & 31) == 0) red[j >> 5] = s;
    __syncthreads();
    const float m = (red[0] + red[1] + red[2] + red[3]) * (1.0f / 128.0f);

    const float d = val - m;
    float s2 = d * d;
    #pragma unroll
    for (int o = 16; o > 0; o >>= 1) s2 += __shfl_xor_sync(0xffffffff, s2, o);
    if ((j & 31) == 0) red2[j >> 5] = s2;
    __syncthreads();
    const float v = (red2[0] + red2[1] + red2[2] + red2[3]) * (1.0f / 128.0f);

    h[(size_t)n * H + j] = g[j] * d * rsqrtf(v + LN_EPS) + bln[j];
}

// ---------------- CSR build ----------------
__global__ void hist_kernel(const int* __restrict__ tgt, int* __restrict__ cnt, int nE)
{
    int e = blockIdx.x * blockDim.x + threadIdx.x;
    if (e < nE) atomicAdd(&cnt[tgt[e]], 1);
}

__device__ void scan_impl(const int* __restrict__ cnt, int* __restrict__ rowptr,
                          int* __restrict__ cursor, int n)
{
    __shared__ int wsum[32];
    __shared__ int tot_s;
    const int tid = threadIdx.x;
    const int lane = tid & 31, w = tid >> 5;
    int carry = 0;
    for (int base = 0; base < n; base += 1024) {
        const int i = base + tid;
        int x = (i < n) ? cnt[i] : 0;
        int v = x;
        #pragma unroll
        for (int off = 1; off < 32; off <<= 1) {
            int t = __shfl_up_sync(0xffffffff, v, off);
            if (lane >= off) v += t;
        }
        if (lane == 31) wsum[w] = v;
        __syncthreads();
        if (w == 0) {
            int t = wsum[lane];
            #pragma unroll
            for (int off = 1; off < 32; off <<= 1) {
                int u = __shfl_up_sync(0xffffffff, t, off);
                if (lane >= off) t += u;
            }
            wsum[lane] = t;
            if (lane == 31) tot_s = t;
        }
        __syncthreads();
        const int incl = v + (w > 0 ? wsum[w - 1] : 0);
        if (i < n) { int ex = carry + incl - x; rowptr[i] = ex; cursor[i] = ex; }
        carry += tot_s;
        __syncthreads();
    }
    if (tid == 0) rowptr[n] = carry;
}

__global__ void scan2_kernel(const int* cA, int* rA, int* uA, int nA,
                             const int* cB, int* rB, int* uB, int nB)
{
    if (blockIdx.x == 0) scan_impl(cA, rA, uA, nA);
    else                 scan_impl(cB, rB, uB, nB);
}

__global__ void fill_kernel(const int* __restrict__ src, const int* __restrict__ tgt,
                            int* __restrict__ cursor, int* __restrict__ list, int nE)
{
    int e = blockIdx.x * blockDim.x + threadIdx.x;
    if (e < nE) {
        int p = atomicAdd(&cursor[tgt[e]], 1);
        list[p] = src[e];
    }
}

// ================= GEMM v4 =================
// Geometry: 256 threads, RT=64 rows/tile, cg=tid&31 -> cols 4cg..4cg+3, rg=tid>>5 -> rows 8rg..8rg+7.
// Wd SMEM layout: Wd[k*128 + (col&3)*32 + (col>>2)] = float2(w,w)
//   -> thread cg reads its 4 (w,w) pairs as 4 x LDS.64 at 8B lane stride: conflict-free.
// XsT: [k][row] with stride 66 (degree-2 gather writes); x row-pairs read as LDS.64,
//   address uniform across warp -> broadcast.
// Inner loop per thread per k: 4 LDS.64 (w) + 4 LDS.64 (x) + 16 FFMA2, zero packing.
#define XST 66
#define RT 64
#define SMEM_GEMM ((2 * 128 * 128 + 128 * XST) * 4)   // 164,864 B

__device__ __forceinline__ void load_wdup(float2* __restrict__ Wd, const float* __restrict__ W,
                                          int ld, int tid)
{
    for (int idx = tid; idx < 128 * 128; idx += 256) {
        const int k = idx >> 7;
        const int cc = idx & 127;
        const float v = W[(size_t)k * ld + cc];
        Wd[k * 128 + (cc & 3) * 32 + (cc >> 2)] = make_float2(v, v);
    }
}

__device__ __forceinline__ void gather_x(float* __restrict__ XsT, const float* __restrict__ A,
                                         int row0, int nRows, int tid)
{
    for (int idx = tid; idx < RT * 128; idx += 256) {
        const int e = idx >> 7;
        const int k = idx & 127;
        int r = row0 + e;
        if (r >= nRows) r = nRows - 1;
        XsT[k * XST + e] = A[(size_t)r * 128 + k];
    }
}

// NCH chunks (even): chunk c < NCH/2 uses (A0, Wa + sub*wstep, ba + sub*128, out0),
// else (A1, Wb + sub*wstep, bb + sub*128, out1), where sub = c % (NCH/2).
// Column offset within out = sub*128 + 4*cg.
template<int NCH, bool ACT>
__global__ void __launch_bounds__(256, 1)
pgemmN_kernel(const float* __restrict__ A0, const float* __restrict__ A1,
              const float* __restrict__ Wa, const float* __restrict__ ba,
              const float* __restrict__ Wb, const float* __restrict__ bb,
              int ldw, int wstep,
              float* __restrict__ out0, float* __restrict__ out1,
              int outW, int nRows)
{
    extern __shared__ float sm[];
    float2* Wd  = (float2*)sm;               // 128*128 float2
    float*  XsT = sm + 2 * 128 * 128;        // 128 * XST

    const int tid = threadIdx.x;
    const int cg = tid & 31;
    const int rg = tid >> 5;

    constexpr int half = NCH / 2;
    const int c   = blockIdx.x % NCH;
    const int bpc = gridDim.x / NCH;
    const int t0  = blockIdx.x / NCH;
    const int sub = c % half;

    const float* A   = (c < half) ? A0 : A1;
    const float* W   = ((c < half) ? Wa : Wb) + (size_t)sub * wstep;
    const float* bp  = (c < half) ? ba : bb;
    float*       out = ((c < half) ? out0 : out1);

    load_wdup(Wd, W, ldw, tid);

    float bcol[4];
    #pragma unroll
    for (int j = 0; j < 4; j++) bcol[j] = bp ? bp[sub * 128 + 4 * cg + j] : 0.f;

    const int nTiles = (nRows + RT - 1) / RT;
    for (int tile = t0; tile < nTiles; tile += bpc) {
        const int row0 = tile * RT;
        __syncthreads();
        gather_x(XsT, A, row0, nRows, tid);
        __syncthreads();

        u64 acc[4][4];
        #pragma unroll
        for (int p = 0; p < 4; p++)
            #pragma unroll
            for (int j = 0; j < 4; j++) acc[p][j] = pack2(bcol[j], bcol[j]);

        #pragma unroll 8
        for (int k = 0; k < 128; k++) {
            const float* xb = &XsT[k * XST + 8 * rg];
            u64 xp[4], wd[4];
            #pragma unroll
            for (int p = 0; p < 4; p++) xp[p] = *(const u64*)(xb + 2 * p);
            #pragma unroll
            for (int j = 0; j < 4; j++) wd[j] = *(const u64*)&Wd[k * 128 + j * 32 + cg];
            #pragma unroll
            for (int p = 0; p < 4; p++)
                #pragma unroll
                for (int j = 0; j < 4; j++) fma2(acc[p][j], xp[p], wd[j]);
        }

        #pragma unroll
        for (int p = 0; p < 4; p++) {
            const float2 v0 = unpack2(acc[p][0]);
            const float2 v1 = unpack2(acc[p][1]);
            const float2 v2 = unpack2(acc[p][2]);
            const float2 v3 = unpack2(acc[p][3]);
            const int r0 = row0 + 8 * rg + 2 * p;
            float* o0 = out + (size_t)r0 * outW + sub * 128 + 4 * cg;
            if (r0 < nRows) {
                float4 o;
                o.x = ACT ? elu_f(v0.x) : v0.x; o.y = ACT ? elu_f(v1.x) : v1.x;
                o.z = ACT ? elu_f(v2.x) : v2.x; o.w = ACT ? elu_f(v3.x) : v3.x;
                *(float4*)o0 = o;
            }
            if (r0 + 1 < nRows) {
                float4 o;
                o.x = ACT ? elu_f(v0.y) : v0.y; o.y = ACT ? elu_f(v1.y) : v1.y;
                o.z = ACT ? elu_f(v2.y) : v2.y; o.w = ACT ? elu_f(v3.y) : v3.y;
                *(float4*)(o0 + outW) = o;
            }
        }
    }
}

// K=256 concat GEMM (node update): two k-stages; Wd reloaded per tile per stage.
template<bool ACT>
__global__ void __launch_bounds__(256, 1)
pgemmK_kernel(const float* __restrict__ A0, const float* __restrict__ A1,
              const float* __restrict__ W, const float* __restrict__ bias,
              float* __restrict__ out, int nRows)
{
    extern __shared__ float sm[];
    float2* Wd  = (float2*)sm;
    float*  XsT = sm + 2 * 128 * 128;

    const int tid = threadIdx.x;
    const int cg = tid & 31;
    const int rg = tid >> 5;

    float bcol[4];
    #pragma unroll
    for (int j = 0; j < 4; j++) bcol[j] = bias[4 * cg + j];

    const int nTiles = (nRows + RT - 1) / RT;
    for (int tile = blockIdx.x; tile < nTiles; tile += gridDim.x) {
        const int row0 = tile * RT;
        u64 acc[4][4];
        #pragma unroll
        for (int p = 0; p < 4; p++)
            #pragma unroll
            for (int j = 0; j < 4; j++) acc[p][j] = pack2(bcol[j], bcol[j]);

        #pragma unroll
        for (int s = 0; s < 2; s++) {
            __syncthreads();
            load_wdup(Wd, W + (size_t)s * 128 * 128, 128, tid);
            gather_x(XsT, s ? A1 : A0, row0, nRows, tid);
            __syncthreads();

            #pragma unroll 8
            for (int k = 0; k < 128; k++) {
                const float* xb = &XsT[k * XST + 8 * rg];
                u64 xp[4], wd[4];
                #pragma unroll
                for (int p = 0; p < 4; p++) xp[p] = *(const u64*)(xb + 2 * p);
                #pragma unroll
                for (int j = 0; j < 4; j++) wd[j] = *(const u64*)&Wd[k * 128 + j * 32 + cg];
                #pragma unroll
                for (int p = 0; p < 4; p++)
                    #pragma unroll
                    for (int j = 0; j < 4; j++) fma2(acc[p][j], xp[p], wd[j]);
            }
        }

        #pragma unroll
        for (int p = 0; p < 4; p++) {
            const float2 v0 = unpack2(acc[p][0]);
            const float2 v1 = unpack2(acc[p][1]);
            const float2 v2 = unpack2(acc[p][2]);
            const float2 v3 = unpack2(acc[p][3]);
            const int r0 = row0 + 8 * rg + 2 * p;
            float* o0 = out + (size_t)r0 * 128 + 4 * cg;
            if (r0 < nRows) {
                float4 o;
                o.x = ACT ? elu_f(v0.x) : v0.x; o.y = ACT ? elu_f(v1.x) : v1.x;
                o.z = ACT ? elu_f(v2.x) : v2.x; o.w = ACT ? elu_f(v3.x) : v3.x;
                *(float4*)o0 = o;
            }
            if (r0 + 1 < nRows) {
                float4 o;
                o.x = ACT ? elu_f(v0.y) : v0.y; o.y = ACT ? elu_f(v1.y) : v1.y;
                o.z = ACT ? elu_f(v2.y) : v2.y; o.w = ACT ? elu_f(v3.y) : v3.y;
                *(float4*)(o0 + 128) = o;
            }
        }
    }
}

// ---------------- aggregate: out[t] = sum_{e in CSR(t)} elu(Psend[src_e] + Ptgt[t] + b) ----------------
__global__ void agg_kernel(const int* __restrict__ rowptr, const int* __restrict__ srcs,
                           const float* __restrict__ Psend, const float* __restrict__ Ptgt,
                           const float* __restrict__ bias, float* __restrict__ out)
{
    const int t = blockIdx.x;
    const int j = threadIdx.x;
    const float base = Ptgt[(size_t)t * 256 + 128 + j] + bias[j];
    const int beg = rowptr[t], end = rowptr[t + 1];
    float s0 = 0.f, s1 = 0.f;
    int i = beg;
    for (; i + 1 < end; i += 2) {
        const int a = srcs[i];
        const int b = srcs[i + 1];
        s0 += elu_f(base + Psend[(size_t)a * 256 + j]);
        s1 += elu_f(base + Psend[(size_t)b * 256 + j]);
    }
    if (i < end) s0 += elu_f(base + Psend[(size_t)srcs[i] * 256 + j]);
    out[(size_t)t * 128 + j] = s0 + s1;
}

// ---------------- GRU combine ----------------
__global__ void gru_combine_kernel(const float* __restrict__ xa, const float* __restrict__ ha,
                                   float* __restrict__ h, int nNodes)
{
    const int idx = blockIdx.x * blockDim.x + threadIdx.x;
    if (idx >= nNodes * 32) return;
    const int n = idx >> 5;
    const int q = (idx & 31) * 4;
    const float4 xz = *(const float4*)&xa[(size_t)n * 384 + q];
    const float4 xr = *(const float4*)&xa[(size_t)n * 384 + 128 + q];
    const float4 xh = *(const float4*)&xa[(size_t)n * 384 + 256 + q];
    const float4 hz = *(const float4*)&ha[(size_t)n * 384 + q];
    const float4 hr = *(const float4*)&ha[(size_t)n * 384 + 128 + q];
    const float4 hh = *(const float4*)&ha[(size_t)n * 384 + 256 + q];
    float4 ho = *(const float4*)&h[(size_t)n * 128 + q];

    float z, r, c;
    z = sig_f(xz.x + hz.x); r = sig_f(xr.x + hr.x); c = tanhf(xh.x + r * hh.x); ho.x = z * ho.x + (1.f - z) * c;
    z = sig_f(xz.y + hz.y); r = sig_f(xr.y + hr.y); c = tanhf(xh.y + r * hh.y); ho.y = z * ho.y + (1.f - z) * c;
    z = sig_f(xz.z + hz.z); r = sig_f(xr.z + hr.z); c = tanhf(xh.z + r * hh.z); ho.z = z * ho.z + (1.f - z) * c;
    z = sig_f(xz.w + hz.w); r = sig_f(xr.w + hr.w); c = tanhf(xh.w + r * hh.w); ho.w = z * ho.w + (1.f - z) * c;
    *(float4*)&h[(size_t)n * 128 + q] = ho;
}

// ---------------- final ----------------
__global__ void final_kernel(const float* __restrict__ hv, const float* __restrict__ Wf,
                             const float* __restrict__ bf, float* __restrict__ out, int n)
{
    const int gw = (blockIdx.x * blockDim.x + threadIdx.x) >> 5;
    const int lane = threadIdx.x & 31;
    if (gw >= n) return;
    const float* row = hv + (size_t)gw * H;
    float s = row[lane] * Wf[lane] + row[lane + 32] * Wf[lane + 32]
            + row[lane + 64] * Wf[lane + 64] + row[lane + 96] * Wf[lane + 96];
    #pragma unroll
    for (int o = 16; o > 0; o >>= 1) s += __shfl_xor_sync(0xffffffff, s, o);
    if (lane == 0) out[gw] = s + bf[0];
}

// ---------------- host ----------------
static inline int mini(int a, int b) { return a < b ? a : b; }

extern "C" void kernel_launch(void* const* d_in, const int* in_sizes, int n_in,
                              void* d_out, int out_size)
{
    const float* check_feats = (const float*)d_in[0];
    const float* var_feats   = (const float*)d_in[1];
    const int*   c2v_src     = (const int*)d_in[2];
    const int*   c2v_tgt     = (const int*)d_in[3];
    const int*   v2c_src     = (const int*)d_in[4];
    const int*   v2c_tgt     = (const int*)d_in[5];
    const float* Wc_in  = (const float*)d_in[6];
    const float* bc_in  = (const float*)d_in[7];
    const float* Wv_in  = (const float*)d_in[8];
    const float* bv_in  = (const float*)d_in[9];
    const float* gc_ln  = (const float*)d_in[10];
    const float* bc_ln  = (const float*)d_in[11];
    const float* gv_ln  = (const float*)d_in[12];
    const float* bv_ln  = (const float*)d_in[13];
    const float* Wmsg_c = (const float*)d_in[14];
    const float* bmsg_c = (const float*)d_in[15];
    const float* Wmsg_v = (const float*)d_in[16];
    const float* bmsg_v = (const float*)d_in[17];
    const float* Wns_c  = (const float*)d_in[18];
    const float* bns_c  = (const float*)d_in[19];
    const float* Wns_v  = (const float*)d_in[20];
    const float* bns_v  = (const float*)d_in[21];
    const float* Wg_c   = (const float*)d_in[22];
    const float* Ug_c   = (const float*)d_in[23];
    const float* bg_c   = (const float*)d_in[24];
    const float* Wg_v   = (const float*)d_in[25];
    const float* Ug_v   = (const float*)d_in[26];
    const float* bg_v   = (const float*)d_in[27];
    const float* Wf     = (const float*)d_in[28];
    const float* bf     = (const float*)d_in[29];

    const int NCn = in_sizes[0];
    const int NVn = in_sizes[1];
    const int E   = in_sizes[2];

    float *hc, *hv, *Pc, *Pv, *aggc, *aggv, *updc, *updv, *xac, *hac, *xav, *hav;
    int *cnt_c, *cnt_v, *rp_c, *rp_v, *cur_c, *cur_v, *el_c, *el_v;
    cudaGetSymbolAddress((void**)&hc,   g_hc);
    cudaGetSymbolAddress((void**)&hv,   g_hv);
    cudaGetSymbolAddress((void**)&Pc,   g_Pc);
    cudaGetSymbolAddress((void**)&Pv,   g_Pv);
    cudaGetSymbolAddress((void**)&aggc, g_aggc);
    cudaGetSymbolAddress((void**)&aggv, g_aggv);
    cudaGetSymbolAddress((void**)&updc, g_updc);
    cudaGetSymbolAddress((void**)&updv, g_updv);
    cudaGetSymbolAddress((void**)&xac,  g_xac);
    cudaGetSymbolAddress((void**)&hac,  g_hac);
    cudaGetSymbolAddress((void**)&xav,  g_xav);
    cudaGetSymbolAddress((void**)&hav,  g_hav);
    cudaGetSymbolAddress((void**)&cnt_c, g_cnt_c);
    cudaGetSymbolAddress((void**)&cnt_v, g_cnt_v);
    cudaGetSymbolAddress((void**)&rp_c,  g_rp_c);
    cudaGetSymbolAddress((void**)&rp_v,  g_rp_v);
    cudaGetSymbolAddress((void**)&cur_c, g_cur_c);
    cudaGetSymbolAddress((void**)&cur_v, g_cur_v);
    cudaGetSymbolAddress((void**)&el_c,  g_el_c);
    cudaGetSymbolAddress((void**)&el_v,  g_el_v);

    auto msgGemm  = pgemmN_kernel<2, false>;
    auto gruGemm  = pgemmN_kernel<6, false>;
    auto nodeGemm = pgemmK_kernel<true>;
    cudaFuncSetAttribute(msgGemm,  cudaFuncAttributeMaxDynamicSharedMemorySize, SMEM_GEMM);
    cudaFuncSetAttribute(gruGemm,  cudaFuncAttributeMaxDynamicSharedMemorySize, SMEM_GEMM);
    cudaFuncSetAttribute(nodeGemm, cudaFuncAttributeMaxDynamicSharedMemorySize, SMEM_GEMM);

    // grids
    const int tV = (NVn + RT - 1) / RT, tC = (NCn + RT - 1) / RT;
    const int gMsgV = 2 * mini(tV, 74), gMsgC = 2 * mini(tC, 74);
    const int gGruV = 6 * mini(tV, 24), gGruC = 6 * mini(tC, 24);
    const int gNodeV = mini(tV, 148),   gNodeC = mini(tC, 148);
    const int gEh = (E + 255) / 256;

    // ---- init node states (also zero CSR counters) ----
    init_kernel<<<NCn, 128>>>(check_feats, Wc_in, bc_in, gc_ln, bc_ln, hc, cnt_c, NCn);
    init_kernel<<<NVn, 128>>>(var_feats,  Wv_in, bv_in, gv_ln, bv_ln, hv, cnt_v, NVn);

    // ---- CSR histogram + scan ----
    hist_kernel<<<gEh, 256>>>(v2c_tgt, cnt_c, E);
    hist_kernel<<<gEh, 256>>>(c2v_tgt, cnt_v, E);
    scan2_kernel<<<2, 1024>>>(cnt_c, rp_c, cur_c, NCn, cnt_v, rp_v, cur_v, NVn);

    bool first = true;
    for (int it = 0; it < NITER; it++) {
        // message projections:
        // Pv[:,0:128] = hv @ Wmsg_c[0:128]   (sender proj, v2c)
        // Pv[:,128:256] = hv @ Wmsg_v[128:256] (receiver proj, c2v)
        msgGemm<<<gMsgV, 256, SMEM_GEMM>>>(
            hv, hv, Wmsg_c, nullptr, Wmsg_v + 128 * 128, nullptr,
            128, 0, Pv, Pv + 128, 256, NVn);
        msgGemm<<<gMsgC, 256, SMEM_GEMM>>>(
            hc, hc, Wmsg_v, nullptr, Wmsg_c + 128 * 128, nullptr,
            128, 0, Pc, Pc + 128, 256, NCn);

        if (first) {
            fill_kernel<<<gEh, 256>>>(v2c_src, v2c_tgt, cur_c, el_c, E);
            fill_kernel<<<gEh, 256>>>(c2v_src, c2v_tgt, cur_v, el_v, E);
            first = false;
        }

        agg_kernel<<<NCn, 128>>>(rp_c, el_c, Pv, Pc, bmsg_c, aggc);
        agg_kernel<<<NVn, 128>>>(rp_v, el_v, Pc, Pv, bmsg_v, aggv);

        nodeGemm<<<gNodeC, 256, SMEM_GEMM>>>(hc, aggc, Wns_c, bns_c, updc, NCn);
        nodeGemm<<<gNodeV, 256, SMEM_GEMM>>>(hv, aggv, Wns_v, bns_v, updv, NVn);

        // GRU gate pre-activations in ONE launch per node set:
        // chunks 0-2: xa = upd @ Wg + bg[0]; chunks 3-5: ha = h @ Ug + bg[1]
        gruGemm<<<gGruC, 256, SMEM_GEMM>>>(
            updc, hc, Wg_c, bg_c, Ug_c, bg_c + 384,
            384, 128, xac, hac, 384, NCn);
        gru_combine_kernel<<<(NCn * 32 + 255) / 256, 256>>>(xac, hac, hc, NCn);

        gruGemm<<<gGruV, 256, SMEM_GEMM>>>(
            updv, hv, Wg_v, bg_v, Ug_v, bg_v + 384,
            384, 128, xav, hav, 384, NVn);
        gru_combine_kernel<<<(NVn * 32 + 255) / 256, 256>>>(xav, hav, hv, NVn);
    }

    final_kernel<<<(NVn * 32 + 127) / 128, 128>>>(hv, Wf, bf, (float*)d_out, NVn);
}